// round 13
// baseline (speedup 1.0000x reference)
#include <cuda_runtime.h>

// Problem constants
#define S_LEN   1024
#define DK      64
#define BH      96
#define NTHREADS 256
#define CTX_ELEMS ((size_t)BH * S_LEN * DK)

// ---- dynamic smem layout (words) ----
// [0, 9216): K double-buffer (stride 68, offsets 0/4352)  -- pass 1
//            V double-buffer (stride 72, offsets 0/4608)  -- pass 2 (same region)
// [9216, 13568): pass 1: Q tile (tf32, stride 68)
//                pass 2: normalized P (tf32, stride 68)
#define KW    (64 * 68)          // 4352
#define VW    (64 * 72)          // 4608
#define OFF_P (2 * VW)           // 9216
#define SMEM_WORDS (2 * VW + 64 * 68)
#define SMEM_BYTES (SMEM_WORDS * 4)   // 54,272 B  -> 4 CTAs/SM = 217 KB

__device__ __forceinline__ unsigned smem_u32(const void* p) {
    unsigned a;
    asm("{ .reg .u64 t; cvta.to.shared.u64 t, %1; cvt.u32.u64 %0, t; }"
        : "=r"(a) : "l"(p));
    return a;
}
__device__ __forceinline__ unsigned f2tf(float f) {
    unsigned u;
    asm("cvt.rna.tf32.f32 %0, %1;" : "=r"(u) : "f"(f));
    return u;
}
__device__ __forceinline__ void cp16(unsigned dst, const void* src) {
    asm volatile("cp.async.cg.shared.global [%0], [%1], 16;"
                 :: "r"(dst), "l"(src) : "memory");
}
#define CP_COMMIT() asm volatile("cp.async.commit_group;" ::: "memory")
#define CP_WAIT0()  asm volatile("cp.async.wait_group 0;" ::: "memory")

__device__ __forceinline__ void mma_tf32(float c[4], const unsigned a[4],
                                         unsigned b0, unsigned b1) {
    asm volatile(
        "mma.sync.aligned.m16n8k8.row.col.f32.tf32.tf32.f32 "
        "{%0,%1,%2,%3}, {%4,%5,%6,%7}, {%8,%9}, {%0,%1,%2,%3};\n"
        : "+f"(c[0]), "+f"(c[1]), "+f"(c[2]), "+f"(c[3])
        : "r"(a[0]), "r"(a[1]), "r"(a[2]), "r"(a[3]), "r"(b0), "r"(b1));
}

// Fused masked attention. R12 structure, but Q fragments live in SMEM (the
// pass-2 P region) instead of registers, enabling 4 CTAs/SM.
__global__ __launch_bounds__(NTHREADS, 4)
void attn_kernel(const float* __restrict__ Q, const float* __restrict__ K,
                 const float* __restrict__ V, const void* __restrict__ maskp,
                 float* __restrict__ ctx_out, float* __restrict__ attn_out)
{
    extern __shared__ __align__(16) unsigned sm[];
    __shared__ float s_rowsum[64];
    __shared__ float s_inv[64];

    const int tid  = threadIdx.x;
    const int w    = tid >> 5;
    const int lane = tid & 31;
    const int mr   = w & 3;        // row group: rows mr*16 .. +15
    const int nc   = w >> 2;       // col group: cols nc*32 .. +31
    const int g    = lane >> 2;
    const int t    = lane & 3;
    const int bh    = blockIdx.y;
    const int qbase = blockIdx.x * 64;

    const size_t qkv_base = (size_t)bh * S_LEN * DK;
    const size_t attn_bh  = (size_t)bh * S_LEN * S_LEN;
    const unsigned smb = smem_u32(sm);
    unsigned* s_qp = sm + OFF_P;   // Q tile in pass 1, P tile in pass 2

    if (tid < 64) s_rowsum[tid] = 0.f;

    // ---- mask dtype probe on first 4KB (word-sized 0/1/1.0f vs packed bytes)
    unsigned other = 0;
    {
        const unsigned* mw = (const unsigned*)maskp;
        #pragma unroll
        for (int i = 0; i < 4; ++i) {
            unsigned x = mw[tid * 4 + i];
            if (x != 0u && x != 1u && x != 0x3F800000u) other = 1;
        }
    }
    const int byte_mode = __syncthreads_or((int)other);

    const unsigned char* mu8  = (const unsigned char*)maskp;
    const int*           mwrd = (const int*)maskp;

    // ---- prologue: prefetch K tile 0 (cp.async) + stage Q tile (tf32) ------
    {
        const float* Kp = K + qkv_base;
        #pragma unroll
        for (int i = 0; i < 4; ++i) {
            int f = i * NTHREADS + tid;
            int r = f >> 4, c = (f & 15) * 4;
            cp16(smb + (unsigned)(r * 68 + c) * 4, Kp + r * DK + c);
        }
        CP_COMMIT();
        const float* Qp = Q + qkv_base + (size_t)qbase * DK;
        #pragma unroll
        for (int i = 0; i < 4; ++i) {
            int f = i * NTHREADS + tid;
            int r = f >> 4, c = (f & 15) * 4;
            float4 v = *(const float4*)(Qp + r * DK + c);
            *(uint4*)&s_qp[r * 68 + c] =
                make_uint4(f2tf(v.x), f2tf(v.y), f2tf(v.z), f2tf(v.w));
        }
    }

    const int row0c = mr * 16 + g;
    const int grow0 = qbase + row0c;
    float rs0 = 0.f, rs1 = 0.f;

    // ======================= PASS 1 ========================================
    for (int kt = 0; kt < 16; ++kt) {
        CP_WAIT0();
        __syncthreads();       // tile kt staged (and Q staged on iter 0)
        const unsigned kb = (unsigned)(kt & 1) * KW;
        if (kt < 15) {         // prefetch tile kt+1 into the other buffer
            const float* Kp = K + qkv_base + (size_t)((kt + 1) * 64) * DK;
            const unsigned nb = (unsigned)((kt + 1) & 1) * KW;
            #pragma unroll
            for (int i = 0; i < 4; ++i) {
                int f = i * NTHREADS + tid;
                int r = f >> 4, c = (f & 15) * 4;
                cp16(smb + (nb + (unsigned)(r * 68 + c)) * 4, Kp + r * DK + c);
            }
            CP_COMMIT();
        }

        // QK^T: A-frags from s_qp (tf32), B-frags raw fp32 K + inline RNA cvt
        float sc[4][4];
        #pragma unroll
        for (int j = 0; j < 4; ++j) { sc[j][0]=0.f; sc[j][1]=0.f; sc[j][2]=0.f; sc[j][3]=0.f; }

        #pragma unroll
        for (int ki = 0; ki < 8; ++ki) {
            int kk = ki * 8 + t;
            unsigned a[4];
            a[0] = s_qp[row0c * 68 + kk];
            a[1] = s_qp[(row0c + 8) * 68 + kk];
            a[2] = s_qp[row0c * 68 + kk + 4];
            a[3] = s_qp[(row0c + 8) * 68 + kk + 4];
            #pragma unroll
            for (int j = 0; j < 4; ++j) {
                int n = nc * 32 + j * 8 + g;
                unsigned b0 = f2tf(__uint_as_float(sm[kb + n * 68 + kk]));
                unsigned b1 = f2tf(__uint_as_float(sm[kb + n * 68 + kk + 4]));
                mma_tf32(sc[j], a, b0, b1);
            }
        }

        // epilogue: mask (streaming), exp, unnormalized attn store, row sums
        #pragma unroll
        for (int j = 0; j < 4; ++j) {
            int col = kt * 64 + nc * 32 + j * 8 + 2 * t;
            size_t off0 = attn_bh + (size_t)grow0 * S_LEN + col;
            size_t off1 = off0 + (size_t)8 * S_LEN;
            unsigned m0, m1, m2, m3;
            if (byte_mode) {
                unsigned short a = __ldcs((const unsigned short*)(mu8 + off0));
                unsigned short b = __ldcs((const unsigned short*)(mu8 + off1));
                m0 = a & 0xFFu; m1 = a >> 8;
                m2 = b & 0xFFu; m3 = b >> 8;
            } else {           // int32 (0/1) and float32 (0.0/1.0): word != 0
                int2 a = __ldcs((const int2*)(mwrd + off0));
                int2 b = __ldcs((const int2*)(mwrd + off1));
                m0 = (unsigned)a.x; m1 = (unsigned)a.y;
                m2 = (unsigned)b.x; m3 = (unsigned)b.y;
            }
            float p0 = m0 ? 0.f : __expf(sc[j][0] * 0.125f);
            float p1 = m1 ? 0.f : __expf(sc[j][1] * 0.125f);
            float p2 = m2 ? 0.f : __expf(sc[j][2] * 0.125f);
            float p3 = m3 ? 0.f : __expf(sc[j][3] * 0.125f);
            rs0 += p0 + p1;
            rs1 += p2 + p3;
            __stcs((float2*)(attn_out + off0), make_float2(p0, p1));
            __stcs((float2*)(attn_out + off1), make_float2(p2, p3));
        }
    }

    // ---- row-sum reduce (quad -> smem across the 2 col-group warps) --------
    rs0 += __shfl_xor_sync(0xFFFFFFFFu, rs0, 1);
    rs0 += __shfl_xor_sync(0xFFFFFFFFu, rs0, 2);
    rs1 += __shfl_xor_sync(0xFFFFFFFFu, rs1, 1);
    rs1 += __shfl_xor_sync(0xFFFFFFFFu, rs1, 2);
    if (t == 0) {
        atomicAdd(&s_rowsum[row0c], rs0);
        atomicAdd(&s_rowsum[row0c + 8], rs1);
    }
    __syncthreads();           // all warps past pass-1 MMAs (K buffers free)

    // prefetch V tile 0 into V-buf0 (overlaps the inv computation)
    {
        const float* Vp = V + qkv_base;
        #pragma unroll
        for (int i = 0; i < 4; ++i) {
            int f = i * NTHREADS + tid;
            int r = f >> 4, c = (f & 15) * 4;
            cp16(smb + (unsigned)(r * 72 + c) * 4, Vp + r * DK + c);
        }
        CP_COMMIT();
    }
    if (tid < 64) s_inv[tid] = 1.0f / s_rowsum[tid];
    __syncthreads();

    // ======================= PASS 2 ========================================
    float oc[4][4];
    #pragma unroll
    for (int j = 0; j < 4; ++j) { oc[j][0]=0.f; oc[j][1]=0.f; oc[j][2]=0.f; oc[j][3]=0.f; }

    for (int kt = 0; kt < 16; ++kt) {
        CP_WAIT0();
        __syncthreads();       // V tile kt visible; all warps past PV of kt-1
        const unsigned vb = (unsigned)(kt & 1) * VW;
        if (kt < 15) {
            const float* Vp = V + qkv_base + (size_t)((kt + 1) * 64) * DK;
            const unsigned nb = (unsigned)((kt + 1) & 1) * VW;
            #pragma unroll
            for (int i = 0; i < 4; ++i) {
                int f = i * NTHREADS + tid;
                int r = f >> 4, c = (f & 15) * 4;
                cp16(smb + (nb + (unsigned)(r * 72 + c)) * 4, Vp + r * DK + c);
            }
            CP_COMMIT();
        }

        // read back unnormalized attn tile (streaming), normalize, rewrite,
        // stash RNA-tf32 P (overwrites the Q region, no longer needed)
        {
            float* Ap = attn_out + attn_bh + (size_t)qbase * S_LEN + kt * 64;
            #pragma unroll
            for (int i = 0; i < 4; ++i) {
                int f = i * NTHREADS + tid;
                int r = f >> 4, c4 = (f & 15) * 4;
                float4 p4 = __ldcs((const float4*)(Ap + (size_t)r * S_LEN + c4));
                float iv = s_inv[r];
                p4.x *= iv; p4.y *= iv; p4.z *= iv; p4.w *= iv;
                __stcs((float4*)(Ap + (size_t)r * S_LEN + c4), p4);
                *(uint4*)&s_qp[r * 68 + c4] =
                    make_uint4(f2tf(p4.x), f2tf(p4.y), f2tf(p4.z), f2tf(p4.w));
            }
        }
        __syncthreads();       // all P staged before cross-warp PV reads

        // PV: A-frags from s_qp (tf32 P), B-frags raw fp32 V + inline RNA cvt
        #pragma unroll
        for (int ki = 0; ki < 8; ++ki) {
            int kk = ki * 8 + t;
            unsigned a[4];
            a[0] = s_qp[row0c * 68 + kk];
            a[1] = s_qp[(row0c + 8) * 68 + kk];
            a[2] = s_qp[row0c * 68 + kk + 4];
            a[3] = s_qp[(row0c + 8) * 68 + kk + 4];
            #pragma unroll
            for (int j = 0; j < 4; ++j) {
                int n = nc * 32 + j * 8 + g;
                unsigned b0 = f2tf(__uint_as_float(sm[vb + kk * 72 + n]));
                unsigned b1 = f2tf(__uint_as_float(sm[vb + (kk + 4) * 72 + n]));
                mma_tf32(oc[j], a, b0, b1);
            }
        }
    }

    // ---- write context -----------------------------------------------------
    const size_t cb = qkv_base + (size_t)grow0 * DK;
    #pragma unroll
    for (int j = 0; j < 4; ++j) {
        int dcol = nc * 32 + j * 8 + 2 * t;
        *(float2*)(ctx_out + cb + dcol)          = make_float2(oc[j][0], oc[j][1]);
        *(float2*)(ctx_out + cb + 8 * DK + dcol) = make_float2(oc[j][2], oc[j][3]);
    }
}

extern "C" void kernel_launch(void* const* d_in, const int* in_sizes, int n_in,
                              void* d_out, int out_size) {
    const float* Q = (const float*)d_in[0];
    const float* K = (const float*)d_in[1];
    const float* V = (const float*)d_in[2];
    const void*  M = d_in[3];

    float* ctx  = (float*)d_out;                 // tuple order: (context, attn)
    float* attn = (float*)d_out + CTX_ELEMS;

    cudaFuncSetAttribute(attn_kernel,
                         cudaFuncAttributeMaxDynamicSharedMemorySize, SMEM_BYTES);

    dim3 grid(S_LEN / 64, BH);                   // (16, 96)
    attn_kernel<<<grid, NTHREADS, SMEM_BYTES>>>(Q, K, V, M, ctx, attn);
}